// round 6
// baseline (speedup 1.0000x reference)
#include <cuda_runtime.h>
#include <math.h>

#define B 4
#define N 64
#define T 256
#define H 256
#define L 5
#define TOPK 8
#define BT (B*T)

#define RB 8            // rows per block in GEMM kernels
#define KK 8            // k-tile
#define NT (H/KK)       // 32 tiles

// k_dots tiling
#define TB 64           // t-tile
#define NG 8            // peers per block

__constant__ int c_lags[L] = {1, 5, 10, 21, 30};

// -------- scratch (device globals: no allocation allowed) --------
__device__ float g_W[H*H];      // wq^T @ wk
__device__ float g_btil[H];     // bq @ wk
__device__ float g_v[H];        // wq^T @ bk
__device__ float g_c0;          // bq . bk
__device__ float g_wvT[H*H];
__device__ float g_w1T[H*H];
__device__ float g_w2T[H*H];
__device__ float g_Qt[BT*H];    // Q tilde
__device__ float g_c[BT];       // Q . bk per row
__device__ float g_lg[BT*N*L];  // full logits
__device__ float g_agg[BT*H];   // weighted sum of selected peer rows
__device__ float g_sw[BT];      // sum of weights

// ---- barrier-free GEMM: thread j accumulates RB rows for column j.
// Weights streamed via LDG with 4-deep register prefetch; X transposed in smem.
__device__ __forceinline__ void gemm_ldg(const float* __restrict__ Wg,
                                         const float* __restrict__ XT,
                                         float* acc, int j) {
    float wb[4][KK];
    #pragma unroll
    for (int p = 0; p < 4; p++)
        #pragma unroll
        for (int hh = 0; hh < KK; hh++) wb[p][hh] = Wg[(p*KK + hh)*H + j];
    #pragma unroll 2
    for (int kt = 0; kt < NT; kt++) {
        int p = kt & 3;
        float w[KK];
        #pragma unroll
        for (int hh = 0; hh < KK; hh++) w[hh] = wb[p][hh];
        if (kt + 4 < NT) {
            #pragma unroll
            for (int hh = 0; hh < KK; hh++)
                wb[p][hh] = Wg[((kt+4)*KK + hh)*H + j];
        }
        #pragma unroll
        for (int hh = 0; hh < KK; hh++) {
            float ww = w[hh];
            float4 x0 = *(const float4*)&XT[(kt*KK + hh)*RB];
            float4 x1 = *(const float4*)&XT[(kt*KK + hh)*RB + 4];
            acc[0] += x0.x*ww; acc[1] += x0.y*ww;
            acc[2] += x0.z*ww; acc[3] += x0.w*ww;
            acc[4] += x1.x*ww; acc[5] += x1.y*ww;
            acc[6] += x1.z*ww; acc[7] += x1.w*ww;
        }
    }
}

// =============== prep: W = wq^T wk, biases folded, transposes ===============
__global__ void k_prep(const float* __restrict__ wq, const float* __restrict__ wk,
                       const float* __restrict__ bq, const float* __restrict__ bk,
                       const float* __restrict__ wv, const float* __restrict__ w1,
                       const float* __restrict__ w2) {
    int bidx = blockIdx.x;
    int j = threadIdx.x;
    if (bidx < H) {
        int h = bidx;
        float acc = 0.f;
        for (int m = 0; m < H; m++) acc += wq[m*H + h] * wk[m*H + j];
        g_W[h*H + j]   = acc;
        g_wvT[h*H + j] = wv[j*H + h];
        g_w1T[h*H + j] = w1[j*H + h];
        g_w2T[h*H + j] = w2[j*H + h];
    } else if (bidx == H) {
        float acc = 0.f;
        for (int m = 0; m < H; m++) acc += bq[m] * wk[m*H + j];
        g_btil[j] = acc;
    } else if (bidx == H + 1) {
        float acc = 0.f;
        for (int m = 0; m < H; m++) acc += wq[m*H + j] * bk[m];
        g_v[j] = acc;
    } else {
        if (j < 32) {
            float s = 0.f;
            for (int i = j; i < H; i += 32) s += bq[i] * bk[i];
            for (int off = 16; off; off >>= 1) s += __shfl_down_sync(0xffffffffu, s, off);
            if (j == 0) g_c0 = s;
        }
    }
}

// ========= Qtilde = target_h @ W + btil ; c = target_h . v + c0 =============
__global__ void k_qtilde(const float* __restrict__ x) {
    __shared__ float s_x[H*RB];         // transposed input
    __shared__ float s_part[8][RB];
    int r0 = blockIdx.x * RB;
    int tid = threadIdx.x;
    int j = tid;
    int wid = tid >> 5, lane = tid & 31;

    float v[RB];
    #pragma unroll
    for (int r = 0; r < RB; r++) v[r] = x[(r0 + r)*H + tid];
    *(float4*)&s_x[tid*RB]     = make_float4(v[0], v[1], v[2], v[3]);
    *(float4*)&s_x[tid*RB + 4] = make_float4(v[4], v[5], v[6], v[7]);

    float gv = g_v[tid];
    #pragma unroll
    for (int r = 0; r < RB; r++) {
        float s = v[r] * gv;
        for (int off = 16; off; off >>= 1) s += __shfl_down_sync(0xffffffffu, s, off);
        if (lane == 0) s_part[wid][r] = s;
    }
    __syncthreads();
    if (tid < RB) {
        float s = g_c0;
        #pragma unroll
        for (int w = 0; w < 8; w++) s += s_part[w][tid];
        g_c[r0 + tid] = s;
    }

    float acc[RB];
    float bt = g_btil[j];
    #pragma unroll
    for (int r = 0; r < RB; r++) acc[r] = bt;
    gemm_ldg(g_W, s_x, acc, j);
    #pragma unroll
    for (int r = 0; r < RB; r++) g_Qt[(r0 + r)*H + j] = acc[r];
}

// ===== k_dots: logits for a (b, 64-t tile, 8-peer group). Each peer row is
// loaded once and dotted against up to 5 staged Q rows (lag diagonal reuse).
__global__ void k_dots(const float* __restrict__ peer,
                       const int* __restrict__ mask) {
    extern __shared__ float sm[];
    float* s_q  = sm;                   // [TB][H]  = 16384
    float* s_lg = sm + TB*H;            // [TB][NG][L] = 2560
    float* s_c  = s_lg + TB*NG*L;       // [TB]
    int*   s_mi = (int*)(s_c + TB);     // [NG]

    int bid = blockIdx.x;
    int ng = bid & 7;
    int tt = (bid >> 3) & 3;
    int b  = bid >> 5;
    int t0 = tt * TB;
    int n0 = ng * NG;
    int tid = threadIdx.x;
    int wid = tid >> 5, lane = tid & 31;

    // stage Q tile + c + mask; init logits tile to -inf
    {
        const float4* src = (const float4*)&g_Qt[(b*T + t0)*H];
        float4* dst = (float4*)s_q;
        for (int i = tid; i < TB*H/4; i += 256) dst[i] = src[i];
        for (int i = tid; i < TB*NG*L; i += 256) s_lg[i] = -INFINITY;
        if (tid < TB) s_c[tid] = g_c[b*T + t0 + tid];
        if (tid < NG) s_mi[tid] = mask[b*N + n0 + tid];
    }
    __syncthreads();

    int tp_lo = t0 - 30; if (tp_lo < 0) tp_lo = 0;
    int tp_hi = t0 + TB - 2;            // t-1 for max t in tile
    int nrows = tp_hi - tp_lo + 1;
    int ntask = NG * nrows;

    for (int task = wid; task < ntask; task += 8) {
        int nl = task / nrows;
        int tp = tp_lo + task - nl*nrows;
        if (!s_mi[nl]) continue;
        const float4* row = (const float4*)(peer + ((size_t)((b*N + n0 + nl)*T + tp)) * H);
        float4 r0 = row[lane];
        float4 r1 = row[lane + 32];
        #pragma unroll
        for (int l = 0; l < L; l++) {
            unsigned tl = (unsigned)(tp + c_lags[l] - t0);
            if (tl < TB) {
                const float4* q4 = (const float4*)&s_q[tl*H];
                float4 q0 = q4[lane];
                float4 q1 = q4[lane + 32];
                float s = r0.x*q0.x + r0.y*q0.y + r0.z*q0.z + r0.w*q0.w
                        + r1.x*q1.x + r1.y*q1.y + r1.z*q1.z + r1.w*q1.w;
                for (int off = 16; off; off >>= 1) s += __shfl_down_sync(0xffffffffu, s, off);
                if (lane == 0)
                    s_lg[(tl*NG + nl)*L + l] = (s + s_c[tl]) * 0.0625f;
            }
        }
    }
    __syncthreads();

    // flush logits tile: g_lg[(b*T+t)*N*L + (n0+nl)*L + l]
    for (int i = tid; i < TB*NG*L; i += 256) {
        int tl = i / (NG*L);
        int rem = i - tl*(NG*L);
        g_lg[(size_t)(b*T + t0 + tl)*(N*L) + n0*L + rem] = s_lg[i];
    }
}

// ===== k_topk: per (b,t): top-8 over 320 logits, softmax, aggregate raw rows
__global__ void k_topk(const float* __restrict__ peer) {
    __shared__ float s_l[N*L];
    __shared__ float swt[TOPK];
    __shared__ int   sidx[TOPK];
    int bt = blockIdx.x;
    int b = bt >> 8;
    int t = bt & 255;
    int tid = threadIdx.x;          // 128 threads
    int wid = tid >> 5, lane = tid & 31;

    for (int i = tid; i < N*L; i += 128) s_l[i] = g_lg[(size_t)bt*(N*L) + i];
    __syncthreads();

    if (wid == 0) {
        float vals[TOPK];
        for (int k = 0; k < TOPK; k++) {
            float bv = -INFINITY; int bi = 0x7fffffff;
            for (int i = lane; i < N*L; i += 32) {
                float v = s_l[i];
                if (v > bv || (v == bv && i < bi)) { bv = v; bi = i; }
            }
            for (int off = 16; off; off >>= 1) {
                float ov = __shfl_down_sync(0xffffffffu, bv, off);
                int   oi = __shfl_down_sync(0xffffffffu, bi, off);
                if (ov > bv || (ov == bv && oi < bi)) { bv = ov; bi = oi; }
            }
            bi = __shfl_sync(0xffffffffu, bi, 0);
            bv = __shfl_sync(0xffffffffu, bv, 0);
            if (lane == 0) { sidx[k] = bi; vals[k] = bv; s_l[bi] = -INFINITY; }
            __syncwarp();
        }
        if (lane == 0) {
            float m = -INFINITY;
            bool allinf = true;
            float safe[TOPK];
            #pragma unroll
            for (int k = 0; k < TOPK; k++) {
                bool ii = isinf(vals[k]);
                allinf = allinf && ii;
                safe[k] = ii ? -1e9f : vals[k];
                if (safe[k] > m) m = safe[k];
            }
            float sw_ = 0.f;
            if (allinf) {
                #pragma unroll
                for (int k = 0; k < TOPK; k++) swt[k] = 0.f;
            } else {
                float e[TOPK]; float tot = 0.f;
                #pragma unroll
                for (int k = 0; k < TOPK; k++) { e[k] = expf(safe[k] - m); tot += e[k]; }
                #pragma unroll
                for (int k = 0; k < TOPK; k++) { float w = e[k] / tot; swt[k] = w; sw_ += w; }
            }
            g_sw[bt] = sw_;
        }
    }
    __syncthreads();

    float acc0 = 0.f, acc1 = 0.f;
    #pragma unroll
    for (int k = 0; k < TOPK; k++) {
        float w = swt[k];
        if (w != 0.f) {
            int d = sidx[k];
            int n = d / L, l = d - n*L;
            int tp = t - c_lags[l];
            const float* row = peer + ((size_t)((b*N + n)*T + tp)) * H;
            acc0 += w * row[tid];
            acc1 += w * row[tid + 128];
        }
    }
    g_agg[bt*H + tid]       = acc0;
    g_agg[bt*H + tid + 128] = acc1;
}

// ===== cs_y = agg@wv^T + sw*bv ; FFN(elu) ; residual ; LayerNorm ; out ======
__global__ void k_ffn(const float* __restrict__ bv, const float* __restrict__ b1,
                      const float* __restrict__ b2, const float* __restrict__ gamma,
                      const float* __restrict__ beta, float* __restrict__ out) {
    __shared__ float s_xa[H*RB];
    __shared__ float s_xb[H*RB];
    __shared__ float s_sw[RB];
    __shared__ float s_ps[8][RB];
    __shared__ float s_pq[8][RB];
    __shared__ float s_mu[RB], s_rs[RB];

    int r0 = blockIdx.x * RB;
    int tid = threadIdx.x;
    int j = tid;
    int wid = tid >> 5, lane = tid & 31;

    {
        float v[RB];
        #pragma unroll
        for (int r = 0; r < RB; r++) v[r] = g_agg[(r0 + r)*H + tid];
        *(float4*)&s_xa[tid*RB]     = make_float4(v[0], v[1], v[2], v[3]);
        *(float4*)&s_xa[tid*RB + 4] = make_float4(v[4], v[5], v[6], v[7]);
    }
    if (tid < RB) s_sw[tid] = g_sw[r0 + tid];
    __syncthreads();

    // GEMM1: cs = agg @ wv^T + sw*bv
    float cs[RB];
    {
        float bvj = bv[j];
        #pragma unroll
        for (int r = 0; r < RB; r++) cs[r] = s_sw[r] * bvj;
        gemm_ldg(g_wvT, s_xa, cs, j);
    }
    *(float4*)&s_xb[j*RB]     = make_float4(cs[0], cs[1], cs[2], cs[3]);
    *(float4*)&s_xb[j*RB + 4] = make_float4(cs[4], cs[5], cs[6], cs[7]);
    __syncthreads();

    // GEMM2: hidden = elu(cs @ w1^T + b1)
    float hd[RB];
    {
        float b1j = b1[j];
        #pragma unroll
        for (int r = 0; r < RB; r++) hd[r] = b1j;
        gemm_ldg(g_w1T, s_xb, hd, j);
        #pragma unroll
        for (int r = 0; r < RB; r++) hd[r] = hd[r] > 0.f ? hd[r] : expm1f(hd[r]);
    }
    *(float4*)&s_xa[j*RB]     = make_float4(hd[0], hd[1], hd[2], hd[3]);
    *(float4*)&s_xa[j*RB + 4] = make_float4(hd[4], hd[5], hd[6], hd[7]);
    __syncthreads();

    // GEMM3: y = cs + hidden @ w2^T + b2
    float y[RB];
    {
        float b2j = b2[j];
        #pragma unroll
        for (int r = 0; r < RB; r++) y[r] = b2j + cs[r];
        gemm_ldg(g_w2T, s_xa, y, j);
    }

    // LayerNorm
    #pragma unroll
    for (int r = 0; r < RB; r++) {
        float s = y[r], q = y[r]*y[r];
        for (int off = 16; off; off >>= 1) {
            s += __shfl_down_sync(0xffffffffu, s, off);
            q += __shfl_down_sync(0xffffffffu, q, off);
        }
        if (lane == 0) { s_ps[wid][r] = s; s_pq[wid][r] = q; }
    }
    __syncthreads();
    if (tid < RB) {
        float s = 0.f, q = 0.f;
        #pragma unroll
        for (int w = 0; w < 8; w++) { s += s_ps[w][tid]; q += s_pq[w][tid]; }
        float mu = s * (1.f/H);
        float var = q * (1.f/H) - mu*mu;
        s_mu[tid] = mu;
        s_rs[tid] = rsqrtf(var + 1e-5f);
    }
    __syncthreads();
    float gj = gamma[j], bj = beta[j];
    #pragma unroll
    for (int r = 0; r < RB; r++)
        out[(r0 + r)*H + j] = (y[r] - s_mu[r]) * s_rs[r] * gj + bj;
}

extern "C" void kernel_launch(void* const* d_in, const int* in_sizes, int n_in,
                              void* d_out, int out_size) {
    const float* target_h = (const float*)d_in[0];
    const float* peer_h   = (const float*)d_in[1];
    const int*   peer_mask = (const int*)d_in[2];
    const float* wq = (const float*)d_in[3];
    const float* bq = (const float*)d_in[4];
    const float* wk = (const float*)d_in[5];
    const float* bk = (const float*)d_in[6];
    const float* wv = (const float*)d_in[7];
    const float* bv = (const float*)d_in[8];
    const float* w1 = (const float*)d_in[9];
    const float* b1 = (const float*)d_in[10];
    const float* w2 = (const float*)d_in[11];
    const float* b2 = (const float*)d_in[12];
    const float* gamma = (const float*)d_in[13];
    const float* beta  = (const float*)d_in[14];
    float* out = (float*)d_out;

    const int DOTS_SMEM = (TB*H + TB*NG*L + TB + NG + 8) * 4;
    cudaFuncSetAttribute(k_dots, cudaFuncAttributeMaxDynamicSharedMemorySize, DOTS_SMEM);

    k_prep<<<H + 3, 256>>>(wq, wk, bq, bk, wv, w1, w2);
    k_qtilde<<<BT/RB, 256>>>(target_h);
    k_dots<<<B * (T/TB) * (N/NG), 256, DOTS_SMEM>>>(peer_h, peer_mask);
    k_topk<<<BT, 128>>>(peer_h);
    k_ffn<<<BT/RB, 256>>>(bv, b1, b2, gamma, beta, out);
}

// round 7
// speedup vs baseline: 1.1511x; 1.1511x over previous
#include <cuda_runtime.h>
#include <math.h>

#define B 4
#define N 64
#define T 256
#define H 256
#define L 5
#define TOPK 8
#define BT (B*T)

#define RB 8            // rows per block in GEMM kernels
#define KK 8            // k-tile
#define NT (H/KK)       // 32 tiles

// k_dots tiling
#define TB 32           // t-tile
#define NG 8            // peers per block

__constant__ int c_lags[L] = {1, 5, 10, 21, 30};

// -------- scratch (device globals: no allocation allowed) --------
__device__ float g_W[H*H];      // wq^T @ wk
__device__ float g_btil[H];     // bq @ wk
__device__ float g_v[H];        // wq^T @ bk
__device__ float g_c0;          // bq . bk
__device__ float g_wvT[H*H];
__device__ float g_w1T[H*H];
__device__ float g_w2T[H*H];
__device__ float g_Qt[BT*H];    // Q tilde
__device__ float g_c[BT];       // Q . bk per row
__device__ float g_lg[BT*N*L];  // full logits
__device__ float g_agg[BT*H];   // weighted sum of selected peer rows
__device__ float g_sw[BT];      // sum of weights

// ---- barrier-free GEMM, 4 rows per thread. Thread j accumulates rows
// [xoff..xoff+4) for column j. Weights streamed via coalesced LDG with
// 4-deep register prefetch; activations transposed in smem [H][RB].
__device__ __forceinline__ void gemm_ldg4(const float* __restrict__ Wg,
                                          const float* __restrict__ XT,
                                          float* acc, int j, int xoff) {
    float wb[4][KK];
    #pragma unroll
    for (int p = 0; p < 4; p++)
        #pragma unroll
        for (int hh = 0; hh < KK; hh++) wb[p][hh] = Wg[(p*KK + hh)*H + j];
    #pragma unroll 2
    for (int kt = 0; kt < NT; kt++) {
        int p = kt & 3;
        float w[KK];
        #pragma unroll
        for (int hh = 0; hh < KK; hh++) w[hh] = wb[p][hh];
        if (kt + 4 < NT) {
            #pragma unroll
            for (int hh = 0; hh < KK; hh++)
                wb[p][hh] = Wg[((kt+4)*KK + hh)*H + j];
        }
        #pragma unroll
        for (int hh = 0; hh < KK; hh++) {
            float ww = w[hh];
            float4 x0 = *(const float4*)&XT[(kt*KK + hh)*RB + xoff];
            acc[0] += x0.x*ww; acc[1] += x0.y*ww;
            acc[2] += x0.z*ww; acc[3] += x0.w*ww;
        }
    }
}

// =============== prep: W = wq^T wk, biases folded, transposes ===============
__global__ void k_prep(const float* __restrict__ wq, const float* __restrict__ wk,
                       const float* __restrict__ bq, const float* __restrict__ bk,
                       const float* __restrict__ wv, const float* __restrict__ w1,
                       const float* __restrict__ w2) {
    int bidx = blockIdx.x;
    int j = threadIdx.x;
    if (bidx < H) {
        int h = bidx;
        __shared__ float s_wq[H];
        s_wq[j] = wq[j*H + h];
        __syncthreads();
        float acc = 0.f;
        #pragma unroll 4
        for (int m = 0; m < H; m++) acc += s_wq[m] * wk[m*H + j];
        g_W[h*H + j]   = acc;
        g_wvT[h*H + j] = wv[j*H + h];
        g_w1T[h*H + j] = w1[j*H + h];
        g_w2T[h*H + j] = w2[j*H + h];
    } else if (bidx == H) {
        float acc = 0.f;
        for (int m = 0; m < H; m++) acc += bq[m] * wk[m*H + j];
        g_btil[j] = acc;
    } else if (bidx == H + 1) {
        float acc = 0.f;
        for (int m = 0; m < H; m++) acc += wq[m*H + j] * bk[m];
        g_v[j] = acc;
    } else {
        if (j < 32) {
            float s = 0.f;
            for (int i = j; i < H; i += 32) s += bq[i] * bk[i];
            for (int off = 16; off; off >>= 1) s += __shfl_down_sync(0xffffffffu, s, off);
            if (j == 0) g_c0 = s;
        }
    }
}

// ========= Qtilde = target_h @ W + btil ; c = target_h . v + c0 =============
// 512 threads: thread = (col j = tid&255, half = tid>>8 -> rows half*4..+4)
__global__ void k_qtilde(const float* __restrict__ x) {
    __shared__ float s_x[H*RB];         // transposed input [H][RB]
    __shared__ float s_part[16][4];
    int r0 = blockIdx.x * RB;
    int tid = threadIdx.x;
    int j = tid & 255;
    int half = tid >> 8;
    int xoff = half * 4;
    int wid = tid >> 5, lane = tid & 31;

    float v[4];
    #pragma unroll
    for (int r = 0; r < 4; r++) v[r] = x[(r0 + xoff + r)*H + j];
    *(float4*)&s_x[j*RB + xoff] = make_float4(v[0], v[1], v[2], v[3]);

    // c partials: reduce v[r]*g_v[j] over j (per half)
    float gv = g_v[j];
    #pragma unroll
    for (int r = 0; r < 4; r++) {
        float s = v[r] * gv;
        for (int off = 16; off; off >>= 1) s += __shfl_down_sync(0xffffffffu, s, off);
        if (lane == 0) s_part[wid][r] = s;
    }
    __syncthreads();
    if (tid < RB) {                     // row = tid
        int hf = tid >> 2, rs = tid & 3;
        float s = g_c0;
        #pragma unroll
        for (int w = 0; w < 8; w++) s += s_part[hf*8 + w][rs];
        g_c[r0 + tid] = s;
    }

    float acc[4];
    float bt = g_btil[j];
    #pragma unroll
    for (int r = 0; r < 4; r++) acc[r] = bt;
    gemm_ldg4(g_W, s_x, acc, j, xoff);
    #pragma unroll
    for (int r = 0; r < 4; r++) g_Qt[(r0 + xoff + r)*H + j] = acc[r];
}

// ===== k_dots: logits for a (b, 32-t tile, 8-peer group). Each peer row is
// loaded once and dotted against up to 5 staged Q rows (lag diagonal reuse).
__global__ void k_dots(const float* __restrict__ peer,
                       const int* __restrict__ mask) {
    extern __shared__ float sm[];
    float* s_q  = sm;                   // [TB][H]
    float* s_lg = sm + TB*H;            // [TB][NG][L]
    float* s_c  = s_lg + TB*NG*L;       // [TB]
    int*   s_mi = (int*)(s_c + TB);     // [NG]

    int bid = blockIdx.x;
    int ng = bid & 7;
    int tt = (bid >> 3) & 7;            // 8 t-tiles of 32
    int b  = bid >> 6;
    int t0 = tt * TB;
    int n0 = ng * NG;
    int tid = threadIdx.x;
    int wid = tid >> 5, lane = tid & 31;

    {
        const float4* src = (const float4*)&g_Qt[(b*T + t0)*H];
        float4* dst = (float4*)s_q;
        for (int i = tid; i < TB*H/4; i += 256) dst[i] = src[i];
        for (int i = tid; i < TB*NG*L; i += 256) s_lg[i] = -INFINITY;
        if (tid < TB) s_c[tid] = g_c[b*T + t0 + tid];
        if (tid < NG) s_mi[tid] = mask[b*N + n0 + tid];
    }
    __syncthreads();

    int tp_lo = t0 - 30; if (tp_lo < 0) tp_lo = 0;
    int tp_hi = t0 + TB - 2;
    int nrows = tp_hi - tp_lo + 1;
    int ntask = NG * nrows;

    for (int task = wid; task < ntask; task += 8) {
        int nl = task / nrows;
        int tp = tp_lo + task - nl*nrows;
        if (!s_mi[nl]) continue;
        const float4* row = (const float4*)(peer + ((size_t)((b*N + n0 + nl)*T + tp)) * H);
        float4 r0 = row[lane];
        float4 r1 = row[lane + 32];
        float s[L]; int tl[L];
        #pragma unroll
        for (int l = 0; l < L; l++) {
            tl[l] = tp + c_lags[l] - t0;
            s[l] = 0.f;
            if ((unsigned)tl[l] < TB) {
                const float4* q4 = (const float4*)&s_q[tl[l]*H];
                float4 q0 = q4[lane];
                float4 q1 = q4[lane + 32];
                s[l] = r0.x*q0.x + r0.y*q0.y + r0.z*q0.z + r0.w*q0.w
                     + r1.x*q1.x + r1.y*q1.y + r1.z*q1.z + r1.w*q1.w;
            }
        }
        // 5 independent butterfly chains -> ILP hides shfl latency
        #pragma unroll
        for (int off = 16; off; off >>= 1) {
            #pragma unroll
            for (int l = 0; l < L; l++)
                s[l] += __shfl_down_sync(0xffffffffu, s[l], off);
        }
        if (lane == 0) {
            #pragma unroll
            for (int l = 0; l < L; l++)
                if ((unsigned)tl[l] < TB)
                    s_lg[(tl[l]*NG + nl)*L + l] = (s[l] + s_c[tl[l]]) * 0.0625f;
        }
    }
    __syncthreads();

    for (int i = tid; i < TB*NG*L; i += 256) {
        int trow = i / (NG*L);
        int rem = i - trow*(NG*L);
        g_lg[(size_t)(b*T + t0 + trow)*(N*L) + n0*L + rem] = s_lg[i];
    }
}

// ===== k_topk: per (b,t): top-8 over 320 logits, softmax, aggregate raw rows
__global__ void k_topk(const float* __restrict__ peer) {
    __shared__ float s_l[N*L];
    __shared__ float swt[TOPK];
    __shared__ int   sidx[TOPK];
    int bt = blockIdx.x;
    int b = bt >> 8;
    int t = bt & 255;
    int tid = threadIdx.x;          // 128 threads
    int wid = tid >> 5, lane = tid & 31;

    for (int i = tid; i < N*L; i += 128) s_l[i] = g_lg[(size_t)bt*(N*L) + i];
    __syncthreads();

    if (wid == 0) {
        float vals[TOPK];
        for (int k = 0; k < TOPK; k++) {
            float bv = -INFINITY; int bi = 0x7fffffff;
            for (int i = lane; i < N*L; i += 32) {
                float v = s_l[i];
                if (v > bv || (v == bv && i < bi)) { bv = v; bi = i; }
            }
            for (int off = 16; off; off >>= 1) {
                float ov = __shfl_down_sync(0xffffffffu, bv, off);
                int   oi = __shfl_down_sync(0xffffffffu, bi, off);
                if (ov > bv || (ov == bv && oi < bi)) { bv = ov; bi = oi; }
            }
            bi = __shfl_sync(0xffffffffu, bi, 0);
            bv = __shfl_sync(0xffffffffu, bv, 0);
            if (lane == 0) { sidx[k] = bi; vals[k] = bv; s_l[bi] = -INFINITY; }
            __syncwarp();
        }
        if (lane == 0) {
            float m = -INFINITY;
            bool allinf = true;
            float safe[TOPK];
            #pragma unroll
            for (int k = 0; k < TOPK; k++) {
                bool ii = isinf(vals[k]);
                allinf = allinf && ii;
                safe[k] = ii ? -1e9f : vals[k];
                if (safe[k] > m) m = safe[k];
            }
            float sw_ = 0.f;
            if (allinf) {
                #pragma unroll
                for (int k = 0; k < TOPK; k++) swt[k] = 0.f;
            } else {
                float e[TOPK]; float tot = 0.f;
                #pragma unroll
                for (int k = 0; k < TOPK; k++) { e[k] = expf(safe[k] - m); tot += e[k]; }
                #pragma unroll
                for (int k = 0; k < TOPK; k++) { float w = e[k] / tot; swt[k] = w; sw_ += w; }
            }
            g_sw[bt] = sw_;
        }
    }
    __syncthreads();

    float acc0 = 0.f, acc1 = 0.f;
    #pragma unroll
    for (int k = 0; k < TOPK; k++) {
        float w = swt[k];
        if (w != 0.f) {
            int d = sidx[k];
            int n = d / L, l = d - n*L;
            int tp = t - c_lags[l];
            const float* row = peer + ((size_t)((b*N + n)*T + tp)) * H;
            acc0 += w * row[tid];
            acc1 += w * row[tid + 128];
        }
    }
    g_agg[bt*H + tid]       = acc0;
    g_agg[bt*H + tid + 128] = acc1;
}

// ===== cs_y = agg@wv^T + sw*bv ; FFN(elu) ; residual ; LayerNorm ; out ======
// 512 threads: thread = (col j, half -> rows half*4..+4)
__global__ void k_ffn(const float* __restrict__ bv, const float* __restrict__ b1,
                      const float* __restrict__ b2, const float* __restrict__ gamma,
                      const float* __restrict__ beta, float* __restrict__ out) {
    __shared__ float s_xa[H*RB];
    __shared__ float s_xb[H*RB];
    __shared__ float s_sw[RB];
    __shared__ float s_ps[16][4];
    __shared__ float s_pq[16][4];
    __shared__ float s_mu[RB], s_rs[RB];

    int r0 = blockIdx.x * RB;
    int tid = threadIdx.x;
    int j = tid & 255;
    int half = tid >> 8;
    int xoff = half * 4;
    int wid = tid >> 5, lane = tid & 31;

    {
        float v[4];
        #pragma unroll
        for (int r = 0; r < 4; r++) v[r] = g_agg[(r0 + xoff + r)*H + j];
        *(float4*)&s_xa[j*RB + xoff] = make_float4(v[0], v[1], v[2], v[3]);
    }
    if (tid < RB) s_sw[tid] = g_sw[r0 + tid];
    __syncthreads();

    // GEMM1: cs = agg @ wv^T + sw*bv
    float cs[4];
    {
        float bvj = bv[j];
        #pragma unroll
        for (int r = 0; r < 4; r++) cs[r] = s_sw[xoff + r] * bvj;
        gemm_ldg4(g_wvT, s_xa, cs, j, xoff);
    }
    *(float4*)&s_xb[j*RB + xoff] = make_float4(cs[0], cs[1], cs[2], cs[3]);
    __syncthreads();

    // GEMM2: hidden = elu(cs @ w1^T + b1)
    float hd[4];
    {
        float b1j = b1[j];
        #pragma unroll
        for (int r = 0; r < 4; r++) hd[r] = b1j;
        gemm_ldg4(g_w1T, s_xb, hd, j, xoff);
        #pragma unroll
        for (int r = 0; r < 4; r++) hd[r] = hd[r] > 0.f ? hd[r] : expm1f(hd[r]);
    }
    __syncthreads();       // s_xa re-use: all reads of s_xa (GEMM1) done
    *(float4*)&s_xa[j*RB + xoff] = make_float4(hd[0], hd[1], hd[2], hd[3]);
    __syncthreads();

    // GEMM3: y = cs + hidden @ w2^T + b2
    float y[4];
    {
        float b2j = b2[j];
        #pragma unroll
        for (int r = 0; r < 4; r++) y[r] = b2j + cs[r];
        gemm_ldg4(g_w2T, s_xa, y, j, xoff);
    }

    // LayerNorm
    #pragma unroll
    for (int r = 0; r < 4; r++) {
        float s = y[r], q = y[r]*y[r];
        for (int off = 16; off; off >>= 1) {
            s += __shfl_down_sync(0xffffffffu, s, off);
            q += __shfl_down_sync(0xffffffffu, q, off);
        }
        if (lane == 0) { s_ps[wid][r] = s; s_pq[wid][r] = q; }
    }
    __syncthreads();
    if (tid < RB) {
        int hf = tid >> 2, rs = tid & 3;
        float s = 0.f, q = 0.f;
        #pragma unroll
        for (int w = 0; w < 8; w++) { s += s_ps[hf*8 + w][rs]; q += s_pq[hf*8 + w][rs]; }
        float mu = s * (1.f/H);
        float var = q * (1.f/H) - mu*mu;
        s_mu[tid] = mu;
        s_rs[tid] = rsqrtf(var + 1e-5f);
    }
    __syncthreads();
    float gj = gamma[j], bj = beta[j];
    #pragma unroll
    for (int r = 0; r < 4; r++)
        out[(r0 + xoff + r)*H + j] = (y[r] - s_mu[xoff + r]) * s_rs[xoff + r] * gj + bj;
}

extern "C" void kernel_launch(void* const* d_in, const int* in_sizes, int n_in,
                              void* d_out, int out_size) {
    const float* target_h = (const float*)d_in[0];
    const float* peer_h   = (const float*)d_in[1];
    const int*   peer_mask = (const int*)d_in[2];
    const float* wq = (const float*)d_in[3];
    const float* bq = (const float*)d_in[4];
    const float* wk = (const float*)d_in[5];
    const float* bk = (const float*)d_in[6];
    const float* wv = (const float*)d_in[7];
    const float* bv = (const float*)d_in[8];
    const float* w1 = (const float*)d_in[9];
    const float* b1 = (const float*)d_in[10];
    const float* w2 = (const float*)d_in[11];
    const float* b2 = (const float*)d_in[12];
    const float* gamma = (const float*)d_in[13];
    const float* beta  = (const float*)d_in[14];
    float* out = (float*)d_out;

    const int DOTS_SMEM = (TB*H + TB*NG*L + TB + NG + 8) * 4;
    cudaFuncSetAttribute(k_dots, cudaFuncAttributeMaxDynamicSharedMemorySize, DOTS_SMEM);

    k_prep<<<H + 3, 256>>>(wq, wk, bq, bk, wv, w1, w2);
    k_qtilde<<<BT/RB, 512>>>(target_h);
    k_dots<<<B * (T/TB) * (N/NG), 256, DOTS_SMEM>>>(peer_h, peer_mask);
    k_topk<<<BT, 128>>>(peer_h);
    k_ffn<<<BT/RB, 512>>>(bv, b1, b2, gamma, beta, out);
}